// round 16
// baseline (speedup 1.0000x reference)
#include <cuda_runtime.h>
#include <cuda_bf16.h>
#include <cuda_fp16.h>
#include <cuda_fp8.h>
#include <cstdint>

#define B_ROWS 8192
#define DDIM   768
#define NLAB   7
#define TEMP   0.3f
#define LAM    0.9f
#define NT     64          // 128-row tile count
#define NTILES 2080        // NT*(NT+1)/2 upper-tri tiles

#define BM 128
#define BN 128
#define BKB 64             // K-chunk bytes (64 fp8 elems)
#define PADB 80            // bytes per smem row (conflict-free ldmatrix)
#define NSTAGE 4
#define STAGEB (256 * PADB)          // 20480 B per stage
#define SMEM_DYN (NSTAGE * STAGEB)   // 81920 B (2 CTAs/SM -> 163840 B)
#define NKC (DDIM / BKB)   // 12

// fp8 encode scale: sqrt(log2(e)/TEMP) -> GEMM acc == S * log2e / T (log2-domain)
#define SCALE8 2.1929394f

#define ZBLK 256
#define ZROWS (B_ROWS / ZBLK)   // 32

// ---------------- static device scratch ----------------
__device__ __nv_bfloat16 g_en[B_ROWS * DDIM];     // bf16 copy (zsum/finalize)
__device__ uint8_t g_en8[B_ROWS * DDIM];          // e4m3, scaled (contrast)
__device__ float g_part[B_ROWS][NT];              // transposed: coalesced finalize reads
__device__ float g_ce[B_ROWS];
__device__ float g_Zpart[ZBLK][NLAB * DDIM];
__device__ float g_Z[NLAB * DDIM];
__device__ int   g_cnt[NLAB];
__device__ float g_fc[2048];
__device__ float g_fe[2048];

// ---------------- helpers ----------------
// ldmatrix on a precomputed shared-memory byte address (no per-call cvta/index math)
__device__ __forceinline__ void ldsm_x4u(uint32_t* r, uint32_t addr) {
    asm volatile("ldmatrix.sync.aligned.m8n8.x4.shared.b16 {%0,%1,%2,%3}, [%4];"
                 : "=r"(r[0]), "=r"(r[1]), "=r"(r[2]), "=r"(r[3]) : "r"(addr));
}

// fp8 MMA with f16 accumulator (2x rate vs f32 acc on legacy pipe)
__device__ __forceinline__ void mma_fp8_h(uint32_t* c, const uint32_t* a, const uint32_t* b) {
    asm volatile(
        "mma.sync.aligned.m16n8k32.row.col.f16.e4m3.e4m3.f16 "
        "{%0,%1}, {%2,%3,%4,%5}, {%6,%7}, {%0,%1};\n"
        : "+r"(c[0]), "+r"(c[1])
        : "r"(a[0]), "r"(a[1]), "r"(a[2]), "r"(a[3]), "r"(b[0]), "r"(b[1]));
}

__device__ __forceinline__ void cp16(void* smem, const void* gmem) {
    uint32_t s = (uint32_t)__cvta_generic_to_shared(smem);
    asm volatile("cp.async.cg.shared.global [%0], [%1], 16;\n" :: "r"(s), "l"(gmem));
}
#define CP_COMMIT() asm volatile("cp.async.commit_group;\n" ::: "memory")

__device__ __forceinline__ uint32_t hexp2u(uint32_t x) {
    uint32_t r;
    asm("ex2.approx.f16x2 %0, %1;" : "=r"(r) : "r"(x));
    return r;
}
__device__ __forceinline__ __half2 h2shfl_xor(__half2 v, int m) {
    uint32_t u = *(uint32_t*)&v;
    u = __shfl_xor_sync(0xffffffffu, u, m);
    return *(__half2*)&u;
}

// ---------------- A) prep: norm(0..1023) | logits(1024..2047) | hist(2048) ----------------
__global__ __launch_bounds__(256)
void prep_kernel(const float* __restrict__ cls,
                 const float* __restrict__ pooled,
                 const float* __restrict__ W,
                 const float* __restrict__ bias,
                 const int* __restrict__ labels,
                 float* __restrict__ out_logits) {
    const int bid = blockIdx.x;
    const int tid = threadIdx.x;
    const int lane = tid & 31;
    const int warp = tid >> 5;

    if (bid < 1024) {
        // ---- norm: 8 rows per block, warp per row, float4 ----
        int row = bid * 8 + warp;
        const float4* r4 = (const float4*)(cls + (size_t)row * DDIM);
        float4 v[6];
        float s = 0.f;
#pragma unroll
        for (int j = 0; j < 6; j++) {
            v[j] = r4[lane + j * 32];
            s += v[j].x * v[j].x + v[j].y * v[j].y + v[j].z * v[j].z + v[j].w * v[j].w;
        }
#pragma unroll
        for (int off = 16; off > 0; off >>= 1) s += __shfl_xor_sync(0xffffffffu, s, off);
        float r = rsqrtf(s);
        uint2* dst = (uint2*)(g_en + (size_t)row * DDIM);
        uint32_t* dst8 = (uint32_t*)(g_en8 + (size_t)row * DDIM);
#pragma unroll
        for (int j = 0; j < 6; j++) {
            float a = v[j].x * r, b = v[j].y * r, c = v[j].z * r, d = v[j].w * r;
            __nv_bfloat162 lo = __floats2bfloat162_rn(a, b);
            __nv_bfloat162 hi = __floats2bfloat162_rn(c, d);
            uint2 u; u.x = *(uint32_t*)&lo; u.y = *(uint32_t*)&hi;
            dst[lane + j * 32] = u;
            uint32_t p = 0;
            p |= (uint32_t)(uint8_t)__nv_cvt_float_to_fp8(a * SCALE8, __NV_SATFINITE, __NV_E4M3);
            p |= (uint32_t)(uint8_t)__nv_cvt_float_to_fp8(b * SCALE8, __NV_SATFINITE, __NV_E4M3) << 8;
            p |= (uint32_t)(uint8_t)__nv_cvt_float_to_fp8(c * SCALE8, __NV_SATFINITE, __NV_E4M3) << 16;
            p |= (uint32_t)(uint8_t)__nv_cvt_float_to_fp8(d * SCALE8, __NV_SATFINITE, __NV_E4M3) << 24;
            dst8[lane + j * 32] = p;
        }
    } else if (bid < 2048) {
        // ---- logits + CE: warp per row ----
        int row = (bid - 1024) * 8 + warp;
        const float* x = pooled + (size_t)row * DDIM;
        float xr[24];
#pragma unroll
        for (int j = 0; j < 24; j++) xr[j] = x[lane + j * 32];
        float lg[NLAB];
#pragma unroll
        for (int l = 0; l < NLAB; l++) {
            const float* wr = W + (size_t)l * DDIM;
            float dot = 0.f;
#pragma unroll
            for (int j = 0; j < 24; j++) dot += xr[j] * wr[lane + j * 32];
#pragma unroll
            for (int off = 16; off > 0; off >>= 1) dot += __shfl_xor_sync(0xffffffffu, dot, off);
            lg[l] = dot + bias[l];
        }
        if (lane == 0) {
            float mx = lg[0];
#pragma unroll
            for (int c = 1; c < NLAB; c++) mx = fmaxf(mx, lg[c]);
            float se = 0.f;
#pragma unroll
            for (int c = 0; c < NLAB; c++) { se += expf(lg[c] - mx); out_logits[(size_t)row * NLAB + c] = lg[c]; }
            g_ce[row] = mx + logf(se) - lg[labels[row]];
        }
    } else {
        // ---- histogram (1 block) ----
        __shared__ int h[NLAB];
        if (tid < NLAB) h[tid] = 0;
        __syncthreads();
        for (int i = tid; i < B_ROWS; i += blockDim.x) atomicAdd(&h[labels[i]], 1);
        __syncthreads();
        if (tid < NLAB) g_cnt[tid] = h[tid];
    }
}

// ---------------- B) contrast tiles (0..2079) | zsum (2080..2335), one launch ----------------
__global__ __launch_bounds__(256, 2)
void contrast_kernel(const int* __restrict__ labels) {
    extern __shared__ __align__(16) char dsm[];   // NSTAGE * STAGEB = 81920 B

    const int tid = threadIdx.x;
    const int lane = tid & 31;
    const int wid = tid >> 5;

    if (blockIdx.x >= NTILES) {
        // ================= zsum block: per-label sums from bf16 g_en =================
        const int zb = blockIdx.x - NTILES;
        const int r0 = zb * ZROWS;
        int* sLab = (int*)dsm;
        if (tid < ZROWS) sLab[tid] = labels[r0 + tid];
        __syncthreads();

        float acc[NLAB][3];
#pragma unroll
        for (int l = 0; l < NLAB; l++)
#pragma unroll
            for (int c = 0; c < 3; c++) acc[l][c] = 0.f;
#pragma unroll 4
        for (int rr = 0; rr < ZROWS; rr++) {
            const int lab = sLab[rr];
            const __nv_bfloat16* row = g_en + (size_t)(r0 + rr) * DDIM;
#pragma unroll
            for (int c = 0; c < 3; c++) {
                float v = __bfloat162float(row[tid + c * 256]);
#pragma unroll
                for (int l = 0; l < NLAB; l++)
                    acc[l][c] += (l == lab) ? v : 0.f;
            }
        }
#pragma unroll
        for (int l = 0; l < NLAB; l++)
#pragma unroll
            for (int c = 0; c < 3; c++)
                g_Zpart[zb][l * DDIM + tid + c * 256] = acc[l][c];
        return;
    }

    // ================= contrast tile =================
    const int wm = wid >> 1;  // 0..3 (rows wm*32)
    const int wn = wid & 1;   // 0..1 (cols wn*64)

    // tile index -> (I, J), I <= J
    int t = blockIdx.x;
    int I = (int)(64.5f - sqrtf(64.5f * 64.5f - 2.0f * (float)t));
    while ((I + 1) * NT - ((I + 1) * I) / 2 <= t) ++I;
    while (I * NT - (I * (I - 1)) / 2 > t) --I;
    const int J = I + (t - (I * NT - (I * (I - 1)) / 2));
    const int rowBase = I * BM;
    const int colBase = J * BN;

    uint32_t acc[2][8][2];
#pragma unroll
    for (int mf = 0; mf < 2; mf++)
#pragma unroll
        for (int nf = 0; nf < 8; nf++) { acc[mf][nf][0] = 0u; acc[mf][nf][1] = 0u; }

    // ---- precomputed ldmatrix smem byte offsets (loop-invariant) ----
    const uint32_t sbase = (uint32_t)__cvta_generic_to_shared(dsm);
    // A fragment: row = wm*32 + mf*16 + (lane&15), kcol(b16) = (lane>>4)*8 -> *2 bytes
    const uint32_t aoff0 = sbase + (uint32_t)((wm * 32 + (lane & 15)) * PADB + (lane >> 4) * 16);
    // B fragment: mi = lane>>3, row = wn*64 + nf2*16 + ((mi>>1)<<3) + (lane&7), kk(b16) = (mi&1)*8 -> *2 bytes
    const int mi = lane >> 3;
    const uint32_t boff0 = sbase + (uint32_t)(128 * PADB +
        (wn * 64 + ((mi >> 1) << 3) + (lane & 7)) * PADB + ((mi & 1) << 3) * 2);

    // ---- prologue: issue stages 0,1 ----
#pragma unroll
    for (int p = 0; p < 2; p++) {
        const uint8_t* base = g_en8 + p * BKB;
        char* dbuf = dsm + p * STAGEB;
#pragma unroll
        for (int it = 0; it < 4; it++) {
            int idx = tid + 256 * it;
            int r = idx >> 2;
            int qb = (idx & 3) * 16;
            int gr = (r < BM) ? (rowBase + r) : (colBase + r - BM);
            cp16(&dbuf[r * PADB + qb], base + (size_t)gr * DDIM + qb);
        }
        CP_COMMIT();
    }

    // ---- mainloop: 12 k-chunks, 4-stage pipeline, ONE sync per kc ----
#pragma unroll 1
    for (int kc = 0; kc < NKC; kc++) {
        if (kc + 2 < NKC) {
            const uint8_t* base = g_en8 + (kc + 2) * BKB;
            char* dbuf = dsm + ((kc + 2) & 3) * STAGEB;
#pragma unroll
            for (int it = 0; it < 4; it++) {
                int idx = tid + 256 * it;
                int r = idx >> 2;
                int qb = (idx & 3) * 16;
                int gr = (r < BM) ? (rowBase + r) : (colBase + r - BM);
                cp16(&dbuf[r * PADB + qb], base + (size_t)gr * DDIM + qb);
            }
            CP_COMMIT();
            asm volatile("cp.async.wait_group 2;\n" ::: "memory");
        } else if (kc + 2 == NKC) {
            asm volatile("cp.async.wait_group 1;\n" ::: "memory");
        } else {
            asm volatile("cp.async.wait_group 0;\n" ::: "memory");
        }
        __syncthreads();

        const uint32_t stage = (uint32_t)(kc & 3) * STAGEB;
#pragma unroll
        for (int ks = 0; ks < 2; ks++) {
            const uint32_t kofs = stage + ks * 32;   // 16 b16 = 32 bytes per ks
            uint32_t a[2][4];
#pragma unroll
            for (int mf = 0; mf < 2; mf++)
                ldsm_x4u(a[mf], aoff0 + kofs + mf * (16 * PADB));
            uint32_t bb[8][2];
#pragma unroll
            for (int nf2 = 0; nf2 < 4; nf2++)
                ldsm_x4u(&bb[nf2 * 2][0], boff0 + kofs + nf2 * (16 * PADB));
#pragma unroll
            for (int mf = 0; mf < 2; mf++)
#pragma unroll
                for (int nf = 0; nf < 8; nf++)
                    mma_fp8_h(acc[mf][nf], a[mf], bb[nf]);
        }
    }

    // ---- epilogue: acc IS log2-domain score in f16x2; e = 2^acc ----
    float* srow = (float*)dsm;         // [2][128]
    float* scol = srow + 2 * 128;      // [4][128]

    if (I != J) {
        __half2 rs2[4];
        __half2 cs2[8];
#pragma unroll
        for (int j = 0; j < 4; j++) rs2[j] = __float2half2_rn(0.f);
#pragma unroll
        for (int j = 0; j < 8; j++) cs2[j] = __float2half2_rn(0.f);

#pragma unroll
        for (int mf = 0; mf < 2; mf++)
#pragma unroll
            for (int nf = 0; nf < 8; nf++) {
                uint32_t ulo = hexp2u(acc[mf][nf][0]);
                uint32_t uhi = hexp2u(acc[mf][nf][1]);
                __half2 elo = *(__half2*)&ulo;
                __half2 ehi = *(__half2*)&uhi;
                rs2[mf * 2 + 0] = __hadd2(rs2[mf * 2 + 0], elo);
                rs2[mf * 2 + 1] = __hadd2(rs2[mf * 2 + 1], ehi);
                cs2[nf] = __hadd2(cs2[nf], __hadd2(elo, ehi));
            }

#pragma unroll
        for (int j = 0; j < 4; j++) {
            rs2[j] = __hadd2(rs2[j], h2shfl_xor(rs2[j], 1));
            rs2[j] = __hadd2(rs2[j], h2shfl_xor(rs2[j], 2));
        }
        if ((lane & 3) == 0) {
#pragma unroll
            for (int j = 0; j < 4; j++) {
                int row = wm * 32 + (j >> 1) * 16 + (lane >> 2) + (j & 1) * 8;
                srow[wn * 128 + row] = __low2float(rs2[j]) + __high2float(rs2[j]);
            }
        }
#pragma unroll
        for (int j = 0; j < 8; j++) {
            cs2[j] = __hadd2(cs2[j], h2shfl_xor(cs2[j], 4));
            cs2[j] = __hadd2(cs2[j], h2shfl_xor(cs2[j], 8));
            cs2[j] = __hadd2(cs2[j], h2shfl_xor(cs2[j], 16));
        }
        if (lane < 4) {
#pragma unroll
            for (int j = 0; j < 8; j++) {
                int col = wn * 64 + j * 8 + lane * 2;
                scol[wm * 128 + col]     = __low2float(cs2[j]);
                scol[wm * 128 + col + 1] = __high2float(cs2[j]);
            }
        }
    } else {
        // diagonal tile: fp32 masked path (64 tiles)
        float rs[4] = {0.f, 0.f, 0.f, 0.f};
        float cs[16];
#pragma unroll
        for (int j = 0; j < 16; j++) cs[j] = 0.f;
        const int r0 = wm * 32 + (lane >> 2);
        const int c0 = wn * 64 + (lane & 3) * 2;
#pragma unroll
        for (int mf = 0; mf < 2; mf++)
#pragma unroll
            for (int nf = 0; nf < 8; nf++) {
                __half2 xlo = *(__half2*)&acc[mf][nf][0];
                __half2 xhi = *(__half2*)&acc[mf][nf][1];
                int rr = r0 + mf * 16, cc = c0 + nf * 8;
                float e0 = (cc     > rr    ) ? exp2f(__low2float(xlo))  : 0.f;
                float e1 = (cc + 1 > rr    ) ? exp2f(__high2float(xlo)) : 0.f;
                float e2 = (cc     > rr + 8) ? exp2f(__low2float(xhi))  : 0.f;
                float e3 = (cc + 1 > rr + 8) ? exp2f(__high2float(xhi)) : 0.f;
                rs[mf * 2 + 0] += e0 + e1;
                rs[mf * 2 + 1] += e2 + e3;
                cs[nf * 2 + 0] += e0 + e2;
                cs[nf * 2 + 1] += e1 + e3;
            }
#pragma unroll
        for (int j = 0; j < 4; j++) {
            rs[j] += __shfl_xor_sync(0xffffffffu, rs[j], 1);
            rs[j] += __shfl_xor_sync(0xffffffffu, rs[j], 2);
        }
#pragma unroll
        for (int j = 0; j < 16; j++) {
            cs[j] += __shfl_xor_sync(0xffffffffu, cs[j], 4);
            cs[j] += __shfl_xor_sync(0xffffffffu, cs[j], 8);
            cs[j] += __shfl_xor_sync(0xffffffffu, cs[j], 16);
        }
        if ((lane & 3) == 0) {
#pragma unroll
            for (int j = 0; j < 4; j++) {
                int row = wm * 32 + (j >> 1) * 16 + (lane >> 2) + (j & 1) * 8;
                srow[wn * 128 + row] = rs[j];
            }
        }
        if (lane < 4) {
#pragma unroll
            for (int j = 0; j < 16; j++) {
                int col = wn * 64 + (j >> 1) * 8 + lane * 2 + (j & 1);
                scol[wm * 128 + col] = cs[j];
            }
        }
    }
    __syncthreads();

    if (tid < 128) {
        float rsum = srow[tid] + srow[128 + tid];
        float csum = scol[tid] + scol[128 + tid] + scol[256 + tid] + scol[384 + tid];
        if (I == J) {
            g_part[rowBase + tid][I] = rsum + csum;
        } else {
            g_part[rowBase + tid][J] = rsum;   // rows of block I, slot J
            g_part[colBase + tid][I] = csum;   // rows of block J, slot I
        }
    }
}

// ---------------- C) Z reduction (single launch) ----------------
__global__ void zred_kernel() {
    int i = blockIdx.x * 256 + threadIdx.x;
    if (i < NLAB * DDIM) {
        float s = 0.f;
#pragma unroll 8
        for (int b = 0; b < ZBLK; b++) s += g_Zpart[b][i];
        g_Z[i] = s;
    }
}

// ---------------- D) finalize part: warp per row, coalesced g_part ----------------
__global__ __launch_bounds__(128)
void finalize_part(const int* __restrict__ labels) {
    __shared__ float sc[4], se[4];
    const int warp = threadIdx.x >> 5;
    const int lane = threadIdx.x & 31;
    const int r = blockIdx.x * 4 + warp;
    const int l = labels[r];

    float es = g_part[r][lane] + g_part[r][lane + 32];
    const __nv_bfloat16* en = g_en + (size_t)r * DDIM;
    const float* z = g_Z + l * DDIM;
    float dot = 0.f, d = 0.f;
#pragma unroll
    for (int j = 0; j < 24; j++) {
        float v = __bfloat162float(en[lane + j * 32]);
        dot += v * z[lane + j * 32];
        d += v * v;
    }
#pragma unroll
    for (int off = 16; off > 0; off >>= 1) {
        es  += __shfl_xor_sync(0xffffffffu, es, off);
        dot += __shfl_xor_sync(0xffffffffu, dot, off);
        d   += __shfl_xor_sync(0xffffffffu, d, off);
    }
    if (lane == 0) {
        float lse = logf(es);
        int ni = g_cnt[l] - 1;
        float pos = (dot - d) * (1.0f / TEMP);
        sc[warp] = (ni > 0) ? (lse - pos / (float)ni) : 0.f;
        se[warp] = g_ce[r];
    }
    __syncthreads();
    if (threadIdx.x == 0) {
        g_fc[blockIdx.x] = sc[0] + sc[1] + sc[2] + sc[3];
        g_fe[blockIdx.x] = se[0] + se[1] + se[2] + se[3];
    }
}

// ---------------- E) combine ----------------
__global__ void finalize_final(float* __restrict__ d_out) {
    __shared__ float sc[1024], se[1024];
    int t = threadIdx.x;
    sc[t] = g_fc[t] + g_fc[t + 1024];
    se[t] = g_fe[t] + g_fe[t + 1024];
    __syncthreads();
    for (int s = 512; s > 0; s >>= 1) {
        if (t < s) { sc[t] += sc[t + s]; se[t] += se[t + s]; }
        __syncthreads();
    }
    if (t == 0) d_out[0] = LAM * sc[0] + (1.0f - LAM) * (se[0] / (float)B_ROWS);
}

// ---------------- launch ----------------
extern "C" void kernel_launch(void* const* d_in, const int* in_sizes, int n_in,
                              void* d_out, int out_size) {
    const float* cls    = (const float*)d_in[0];
    const float* pooled = (const float*)d_in[1];
    const int*   labels = (const int*)d_in[2];
    const float* W      = (const float*)d_in[3];
    const float* bias   = (const float*)d_in[4];
    float* out = (float*)d_out;   // [0] = loss, [1..] = logits

    cudaFuncSetAttribute(contrast_kernel,
                         cudaFuncAttributeMaxDynamicSharedMemorySize, SMEM_DYN);

    prep_kernel<<<2049, 256>>>(cls, pooled, W, bias, labels, out + 1);   // slot 0
    contrast_kernel<<<NTILES + ZBLK, 256, SMEM_DYN>>>(labels);           // slot 1
    zred_kernel<<<(NLAB * DDIM + 255) / 256, 256>>>();                   // slot 2
    finalize_part<<<2048, 128>>>(labels);                                // slot 3
    finalize_final<<<1, 1024>>>(out);                                    // slot 4
}

// round 17
// speedup vs baseline: 1.0211x; 1.0211x over previous
#include <cuda_runtime.h>
#include <cuda_bf16.h>
#include <cuda_fp16.h>
#include <cuda_fp8.h>
#include <cstdint>

#define B_ROWS 8192
#define DDIM   768
#define NLAB   7
#define TEMP   0.3f
#define LAM    0.9f
#define NT     64          // 128-row tile count
#define NTILES 2080        // NT*(NT+1)/2 upper-tri tiles

#define BM 128
#define BN 128
#define BKB 64             // K-chunk bytes (64 fp8 elems)
#define PADB 80            // bytes per smem row (conflict-free ldmatrix)
#define NSTAGE 4
#define STAGEB (256 * PADB)          // 20480 B per stage
#define SMEM_DYN (NSTAGE * STAGEB)   // 81920 B (2 CTAs/SM -> 163840 B)
#define NKC (DDIM / BKB)   // 12

// fp8 encode scale: sqrt(log2(e)/TEMP) -> GEMM acc == S * log2e / T (log2-domain)
#define SCALE8 2.1929394f

#define ZBLK 256
#define ZROWS (B_ROWS / ZBLK)   // 32

// ---------------- static device scratch ----------------
__device__ __nv_bfloat16 g_en[B_ROWS * DDIM];     // bf16 copy (zsum/finalize)
__device__ uint8_t g_en8[B_ROWS * DDIM];          // e4m3, scaled (contrast)
__device__ float g_part[B_ROWS][NT];              // transposed: coalesced finalize reads
__device__ float g_ce[B_ROWS];
__device__ float g_Zpart[ZBLK][NLAB * DDIM];
__device__ float g_Z[NLAB * DDIM];
__device__ int   g_cnt[NLAB];
__device__ float g_fc[2048];
__device__ float g_fe[2048];

// ---------------- helpers ----------------
__device__ __forceinline__ void ldsm_x4(uint32_t* r, const void* p) {
    uint32_t addr = (uint32_t)__cvta_generic_to_shared(p);
    asm volatile("ldmatrix.sync.aligned.m8n8.x4.shared.b16 {%0,%1,%2,%3}, [%4];"
                 : "=r"(r[0]), "=r"(r[1]), "=r"(r[2]), "=r"(r[3]) : "r"(addr));
}

// fp8 MMA with f16 accumulator (2x rate vs f32 acc on legacy pipe)
__device__ __forceinline__ void mma_fp8_h(uint32_t* c, const uint32_t* a, const uint32_t* b) {
    asm volatile(
        "mma.sync.aligned.m16n8k32.row.col.f16.e4m3.e4m3.f16 "
        "{%0,%1}, {%2,%3,%4,%5}, {%6,%7}, {%0,%1};\n"
        : "+r"(c[0]), "+r"(c[1])
        : "r"(a[0]), "r"(a[1]), "r"(a[2]), "r"(a[3]), "r"(b[0]), "r"(b[1]));
}

__device__ __forceinline__ void cp16(void* smem, const void* gmem) {
    uint32_t s = (uint32_t)__cvta_generic_to_shared(smem);
    asm volatile("cp.async.cg.shared.global [%0], [%1], 16;\n" :: "r"(s), "l"(gmem));
}
#define CP_COMMIT() asm volatile("cp.async.commit_group;\n" ::: "memory")

__device__ __forceinline__ uint32_t hexp2u(uint32_t x) {
    uint32_t r;
    asm("ex2.approx.f16x2 %0, %1;" : "=r"(r) : "r"(x));
    return r;
}
__device__ __forceinline__ __half2 h2shfl_xor(__half2 v, int m) {
    uint32_t u = *(uint32_t*)&v;
    u = __shfl_xor_sync(0xffffffffu, u, m);
    return *(__half2*)&u;
}
// bf16 (as u16) -> f32, exact
__device__ __forceinline__ float bf2f(uint32_t h) { return __uint_as_float(h << 16); }

// ---------------- A) prep: norm(0..1023) | logits(1024..2047) | hist(2048) ----------------
__global__ __launch_bounds__(256)
void prep_kernel(const float* __restrict__ cls,
                 const float* __restrict__ pooled,
                 const float* __restrict__ W,
                 const float* __restrict__ bias,
                 const int* __restrict__ labels,
                 float* __restrict__ out_logits) {
    const int bid = blockIdx.x;
    const int tid = threadIdx.x;
    const int lane = tid & 31;
    const int warp = tid >> 5;

    if (bid < 1024) {
        // ---- norm: 8 rows per block, warp per row, float4 ----
        int row = bid * 8 + warp;
        const float4* r4 = (const float4*)(cls + (size_t)row * DDIM);
        float4 v[6];
        float s = 0.f;
#pragma unroll
        for (int j = 0; j < 6; j++) {
            v[j] = r4[lane + j * 32];
            s += v[j].x * v[j].x + v[j].y * v[j].y + v[j].z * v[j].z + v[j].w * v[j].w;
        }
#pragma unroll
        for (int off = 16; off > 0; off >>= 1) s += __shfl_xor_sync(0xffffffffu, s, off);
        float r = rsqrtf(s);
        uint2* dst = (uint2*)(g_en + (size_t)row * DDIM);
        uint32_t* dst8 = (uint32_t*)(g_en8 + (size_t)row * DDIM);
#pragma unroll
        for (int j = 0; j < 6; j++) {
            float a = v[j].x * r, b = v[j].y * r, c = v[j].z * r, d = v[j].w * r;
            __nv_bfloat162 lo = __floats2bfloat162_rn(a, b);
            __nv_bfloat162 hi = __floats2bfloat162_rn(c, d);
            uint2 u; u.x = *(uint32_t*)&lo; u.y = *(uint32_t*)&hi;
            dst[lane + j * 32] = u;
            uint32_t p = 0;
            p |= (uint32_t)(uint8_t)__nv_cvt_float_to_fp8(a * SCALE8, __NV_SATFINITE, __NV_E4M3);
            p |= (uint32_t)(uint8_t)__nv_cvt_float_to_fp8(b * SCALE8, __NV_SATFINITE, __NV_E4M3) << 8;
            p |= (uint32_t)(uint8_t)__nv_cvt_float_to_fp8(c * SCALE8, __NV_SATFINITE, __NV_E4M3) << 16;
            p |= (uint32_t)(uint8_t)__nv_cvt_float_to_fp8(d * SCALE8, __NV_SATFINITE, __NV_E4M3) << 24;
            dst8[lane + j * 32] = p;
        }
    } else if (bid < 2048) {
        // ---- logits + CE: warp per row ----
        int row = (bid - 1024) * 8 + warp;
        const float* x = pooled + (size_t)row * DDIM;
        float xr[24];
#pragma unroll
        for (int j = 0; j < 24; j++) xr[j] = x[lane + j * 32];
        float lg[NLAB];
#pragma unroll
        for (int l = 0; l < NLAB; l++) {
            const float* wr = W + (size_t)l * DDIM;
            float dot = 0.f;
#pragma unroll
            for (int j = 0; j < 24; j++) dot += xr[j] * wr[lane + j * 32];
#pragma unroll
            for (int off = 16; off > 0; off >>= 1) dot += __shfl_xor_sync(0xffffffffu, dot, off);
            lg[l] = dot + bias[l];
        }
        if (lane == 0) {
            float mx = lg[0];
#pragma unroll
            for (int c = 1; c < NLAB; c++) mx = fmaxf(mx, lg[c]);
            float se = 0.f;
#pragma unroll
            for (int c = 0; c < NLAB; c++) { se += expf(lg[c] - mx); out_logits[(size_t)row * NLAB + c] = lg[c]; }
            g_ce[row] = mx + logf(se) - lg[labels[row]];
        }
    } else {
        // ---- histogram (1 block) ----
        __shared__ int h[NLAB];
        if (tid < NLAB) h[tid] = 0;
        __syncthreads();
        for (int i = tid; i < B_ROWS; i += blockDim.x) atomicAdd(&h[labels[i]], 1);
        __syncthreads();
        if (tid < NLAB) g_cnt[tid] = h[tid];
    }
}

// ---------------- B) contrast tiles (0..2079) | zsum (2080..2335), one launch ----------------
__global__ __launch_bounds__(256, 2)
void contrast_kernel(const int* __restrict__ labels) {
    extern __shared__ __align__(16) char dsm[];   // NSTAGE * STAGEB = 81920 B

    const int tid = threadIdx.x;
    const int lane = tid & 31;
    const int wid = tid >> 5;

    if (blockIdx.x >= NTILES) {
        // ================= zsum block: per-label sums from bf16 g_en =================
        const int zb = blockIdx.x - NTILES;
        const int r0 = zb * ZROWS;
        int* sLab = (int*)dsm;
        if (tid < ZROWS) sLab[tid] = labels[r0 + tid];
        __syncthreads();

        float acc[NLAB][3];
#pragma unroll
        for (int l = 0; l < NLAB; l++)
#pragma unroll
            for (int c = 0; c < 3; c++) acc[l][c] = 0.f;
#pragma unroll 4
        for (int rr = 0; rr < ZROWS; rr++) {
            const int lab = sLab[rr];
            const __nv_bfloat16* row = g_en + (size_t)(r0 + rr) * DDIM;
#pragma unroll
            for (int c = 0; c < 3; c++) {
                float v = __bfloat162float(row[tid + c * 256]);
#pragma unroll
                for (int l = 0; l < NLAB; l++)
                    acc[l][c] += (l == lab) ? v : 0.f;
            }
        }
#pragma unroll
        for (int l = 0; l < NLAB; l++)
#pragma unroll
            for (int c = 0; c < 3; c++)
                g_Zpart[zb][l * DDIM + tid + c * 256] = acc[l][c];
        return;
    }

    // ================= contrast tile =================
    const int wm = wid >> 1;  // 0..3 (rows wm*32)
    const int wn = wid & 1;   // 0..1 (cols wn*64)

    // tile index -> (I, J), I <= J
    int t = blockIdx.x;
    int I = (int)(64.5f - sqrtf(64.5f * 64.5f - 2.0f * (float)t));
    while ((I + 1) * NT - ((I + 1) * I) / 2 <= t) ++I;
    while (I * NT - (I * (I - 1)) / 2 > t) --I;
    const int J = I + (t - (I * NT - (I * (I - 1)) / 2));
    const int rowBase = I * BM;
    const int colBase = J * BN;

    uint32_t acc[2][8][2];
#pragma unroll
    for (int mf = 0; mf < 2; mf++)
#pragma unroll
        for (int nf = 0; nf < 8; nf++) { acc[mf][nf][0] = 0u; acc[mf][nf][1] = 0u; }

    // ---- prologue: issue stages 0,1 ----
#pragma unroll
    for (int p = 0; p < 2; p++) {
        const uint8_t* base = g_en8 + p * BKB;
        char* dbuf = dsm + p * STAGEB;
#pragma unroll
        for (int it = 0; it < 4; it++) {
            int idx = tid + 256 * it;
            int r = idx >> 2;
            int qb = (idx & 3) * 16;
            int gr = (r < BM) ? (rowBase + r) : (colBase + r - BM);
            cp16(&dbuf[r * PADB + qb], base + (size_t)gr * DDIM + qb);
        }
        CP_COMMIT();
    }

    // ---- mainloop: 12 k-chunks, 4-stage pipeline, ONE sync per kc ----
    // Safety: write target (kc+2)%4 was last read at iter kc-2; the barrier at
    // iter kc-1 orders every warp's kc-2 reads before any warp's kc writes.
#pragma unroll 1
    for (int kc = 0; kc < NKC; kc++) {
        if (kc + 2 < NKC) {
            const uint8_t* base = g_en8 + (kc + 2) * BKB;
            char* dbuf = dsm + ((kc + 2) & 3) * STAGEB;
#pragma unroll
            for (int it = 0; it < 4; it++) {
                int idx = tid + 256 * it;
                int r = idx >> 2;
                int qb = (idx & 3) * 16;
                int gr = (r < BM) ? (rowBase + r) : (colBase + r - BM);
                cp16(&dbuf[r * PADB + qb], base + (size_t)gr * DDIM + qb);
            }
            CP_COMMIT();
            asm volatile("cp.async.wait_group 2;\n" ::: "memory");
        } else if (kc + 2 == NKC) {
            asm volatile("cp.async.wait_group 1;\n" ::: "memory");
        } else {
            asm volatile("cp.async.wait_group 0;\n" ::: "memory");
        }
        __syncthreads();

        const char* sA = dsm + (kc & 3) * STAGEB;
        const char* sB = sA + 128 * PADB;
#pragma unroll
        for (int ks = 0; ks < 2; ks++) {
            uint32_t a[2][4];
#pragma unroll
            for (int mf = 0; mf < 2; mf++) {
                int row = wm * 32 + mf * 16 + (lane & 15);
                int kcol = ks * 16 + (lane >> 4) * 8;
                ldsm_x4(a[mf], (const __nv_bfloat16*)(sA + row * PADB) + kcol);
            }
            uint32_t bb[8][2];
#pragma unroll
            for (int nf2 = 0; nf2 < 4; nf2++) {
                int mi = lane >> 3;
                int rrow = wn * 64 + nf2 * 16 + ((mi >> 1) << 3) + (lane & 7);
                int kk = ks * 16 + ((mi & 1) << 3);
                ldsm_x4(&bb[nf2 * 2][0], (const __nv_bfloat16*)(sB + rrow * PADB) + kk);
            }
#pragma unroll
            for (int mf = 0; mf < 2; mf++)
#pragma unroll
                for (int nf = 0; nf < 8; nf++)
                    mma_fp8_h(acc[mf][nf], a[mf], bb[nf]);
        }
    }

    // ---- epilogue: acc IS log2-domain score in f16x2; e = 2^acc ----
    float* srow = (float*)dsm;         // [2][128]
    float* scol = srow + 2 * 128;      // [4][128]

    if (I != J) {
        __half2 rs2[4];
        __half2 cs2[8];
#pragma unroll
        for (int j = 0; j < 4; j++) rs2[j] = __float2half2_rn(0.f);
#pragma unroll
        for (int j = 0; j < 8; j++) cs2[j] = __float2half2_rn(0.f);

#pragma unroll
        for (int mf = 0; mf < 2; mf++)
#pragma unroll
            for (int nf = 0; nf < 8; nf++) {
                uint32_t ulo = hexp2u(acc[mf][nf][0]);
                uint32_t uhi = hexp2u(acc[mf][nf][1]);
                __half2 elo = *(__half2*)&ulo;
                __half2 ehi = *(__half2*)&uhi;
                rs2[mf * 2 + 0] = __hadd2(rs2[mf * 2 + 0], elo);
                rs2[mf * 2 + 1] = __hadd2(rs2[mf * 2 + 1], ehi);
                cs2[nf] = __hadd2(cs2[nf], __hadd2(elo, ehi));
            }

#pragma unroll
        for (int j = 0; j < 4; j++) {
            rs2[j] = __hadd2(rs2[j], h2shfl_xor(rs2[j], 1));
            rs2[j] = __hadd2(rs2[j], h2shfl_xor(rs2[j], 2));
        }
        if ((lane & 3) == 0) {
#pragma unroll
            for (int j = 0; j < 4; j++) {
                int row = wm * 32 + (j >> 1) * 16 + (lane >> 2) + (j & 1) * 8;
                srow[wn * 128 + row] = __low2float(rs2[j]) + __high2float(rs2[j]);
            }
        }
#pragma unroll
        for (int j = 0; j < 8; j++) {
            cs2[j] = __hadd2(cs2[j], h2shfl_xor(cs2[j], 4));
            cs2[j] = __hadd2(cs2[j], h2shfl_xor(cs2[j], 8));
            cs2[j] = __hadd2(cs2[j], h2shfl_xor(cs2[j], 16));
        }
        if (lane < 4) {
#pragma unroll
            for (int j = 0; j < 8; j++) {
                int col = wn * 64 + j * 8 + lane * 2;
                scol[wm * 128 + col]     = __low2float(cs2[j]);
                scol[wm * 128 + col + 1] = __high2float(cs2[j]);
            }
        }
    } else {
        // diagonal tile: fp32 masked path (64 tiles)
        float rs[4] = {0.f, 0.f, 0.f, 0.f};
        float cs[16];
#pragma unroll
        for (int j = 0; j < 16; j++) cs[j] = 0.f;
        const int r0 = wm * 32 + (lane >> 2);
        const int c0 = wn * 64 + (lane & 3) * 2;
#pragma unroll
        for (int mf = 0; mf < 2; mf++)
#pragma unroll
            for (int nf = 0; nf < 8; nf++) {
                __half2 xlo = *(__half2*)&acc[mf][nf][0];
                __half2 xhi = *(__half2*)&acc[mf][nf][1];
                int rr = r0 + mf * 16, cc = c0 + nf * 8;
                float e0 = (cc     > rr    ) ? exp2f(__low2float(xlo))  : 0.f;
                float e1 = (cc + 1 > rr    ) ? exp2f(__high2float(xlo)) : 0.f;
                float e2 = (cc     > rr + 8) ? exp2f(__low2float(xhi))  : 0.f;
                float e3 = (cc + 1 > rr + 8) ? exp2f(__high2float(xhi)) : 0.f;
                rs[mf * 2 + 0] += e0 + e1;
                rs[mf * 2 + 1] += e2 + e3;
                cs[nf * 2 + 0] += e0 + e2;
                cs[nf * 2 + 1] += e1 + e3;
            }
#pragma unroll
        for (int j = 0; j < 4; j++) {
            rs[j] += __shfl_xor_sync(0xffffffffu, rs[j], 1);
            rs[j] += __shfl_xor_sync(0xffffffffu, rs[j], 2);
        }
#pragma unroll
        for (int j = 0; j < 16; j++) {
            cs[j] += __shfl_xor_sync(0xffffffffu, cs[j], 4);
            cs[j] += __shfl_xor_sync(0xffffffffu, cs[j], 8);
            cs[j] += __shfl_xor_sync(0xffffffffu, cs[j], 16);
        }
        if ((lane & 3) == 0) {
#pragma unroll
            for (int j = 0; j < 4; j++) {
                int row = wm * 32 + (j >> 1) * 16 + (lane >> 2) + (j & 1) * 8;
                srow[wn * 128 + row] = rs[j];
            }
        }
        if (lane < 4) {
#pragma unroll
            for (int j = 0; j < 16; j++) {
                int col = wn * 64 + (j >> 1) * 8 + lane * 2 + (j & 1);
                scol[wm * 128 + col] = cs[j];
            }
        }
    }
    __syncthreads();

    if (tid < 128) {
        float rsum = srow[tid] + srow[128 + tid];
        float csum = scol[tid] + scol[128 + tid] + scol[256 + tid] + scol[384 + tid];
        if (I == J) {
            g_part[rowBase + tid][I] = rsum + csum;
        } else {
            g_part[rowBase + tid][J] = rsum;   // rows of block I, slot J
            g_part[colBase + tid][I] = csum;   // rows of block J, slot I
        }
    }
}

// ---------------- C) Z reduction (single launch) ----------------
__global__ void zred_kernel() {
    int i = blockIdx.x * 256 + threadIdx.x;
    if (i < NLAB * DDIM) {
        float s = 0.f;
#pragma unroll 8
        for (int b = 0; b < ZBLK; b++) s += g_Zpart[b][i];
        g_Z[i] = s;
    }
}

// ---------------- D) finalize part: warp per row, vectorized loads ----------------
__global__ __launch_bounds__(128)
void finalize_part(const int* __restrict__ labels) {
    __shared__ float sc[4], se[4];
    const int warp = threadIdx.x >> 5;
    const int lane = threadIdx.x & 31;
    const int r = blockIdx.x * 4 + warp;
    const int l = labels[r];

    // exp-sum over 64 tile slots: coalesced 256B line per warp
    float es = g_part[r][lane] + g_part[r][lane + 32];

    // pos dot: en_r . Z[l] and ||en_r||^2, uint4 (8 bf16) + float4 vector loads
    const uint4* en4 = (const uint4*)(g_en + (size_t)r * DDIM);
    const float4* z4 = (const float4*)(g_Z + (size_t)l * DDIM);
    float dot = 0.f, d = 0.f;
#pragma unroll
    for (int k = 0; k < 3; k++) {
        const int i8 = lane + k * 32;          // uint4 index (8 bf16 each)
        uint4 u = en4[i8];
        float4 za = z4[i8 * 2];
        float4 zb = z4[i8 * 2 + 1];
        float e0 = bf2f(u.x & 0xffffu), e1 = bf2f(u.x >> 16);
        float e2 = bf2f(u.y & 0xffffu), e3 = bf2f(u.y >> 16);
        float e4 = bf2f(u.z & 0xffffu), e5 = bf2f(u.z >> 16);
        float e6 = bf2f(u.w & 0xffffu), e7 = bf2f(u.w >> 16);
        dot += e0 * za.x + e1 * za.y + e2 * za.z + e3 * za.w
             + e4 * zb.x + e5 * zb.y + e6 * zb.z + e7 * zb.w;
        d += e0 * e0 + e1 * e1 + e2 * e2 + e3 * e3
           + e4 * e4 + e5 * e5 + e6 * e6 + e7 * e7;
    }
#pragma unroll
    for (int off = 16; off > 0; off >>= 1) {
        es  += __shfl_xor_sync(0xffffffffu, es, off);
        dot += __shfl_xor_sync(0xffffffffu, dot, off);
        d   += __shfl_xor_sync(0xffffffffu, d, off);
    }
    if (lane == 0) {
        float lse = logf(es);
        int ni = g_cnt[l] - 1;
        float pos = (dot - d) * (1.0f / TEMP);
        sc[warp] = (ni > 0) ? (lse - pos / (float)ni) : 0.f;
        se[warp] = g_ce[r];
    }
    __syncthreads();
    if (threadIdx.x == 0) {
        g_fc[blockIdx.x] = sc[0] + sc[1] + sc[2] + sc[3];
        g_fe[blockIdx.x] = se[0] + se[1] + se[2] + se[3];
    }
}

// ---------------- E) combine ----------------
__global__ void finalize_final(float* __restrict__ d_out) {
    __shared__ float sc[1024], se[1024];
    int t = threadIdx.x;
    sc[t] = g_fc[t] + g_fc[t + 1024];
    se[t] = g_fe[t] + g_fe[t + 1024];
    __syncthreads();
    for (int s = 512; s > 0; s >>= 1) {
        if (t < s) { sc[t] += sc[t + s]; se[t] += se[t + s]; }
        __syncthreads();
    }
    if (t == 0) d_out[0] = LAM * sc[0] + (1.0f - LAM) * (se[0] / (float)B_ROWS);
}

// ---------------- launch ----------------
extern "C" void kernel_launch(void* const* d_in, const int* in_sizes, int n_in,
                              void* d_out, int out_size) {
    const float* cls    = (const float*)d_in[0];
    const float* pooled = (const float*)d_in[1];
    const int*   labels = (const int*)d_in[2];
    const float* W      = (const float*)d_in[3];
    const float* bias   = (const float*)d_in[4];
    float* out = (float*)d_out;   // [0] = loss, [1..] = logits

    cudaFuncSetAttribute(contrast_kernel,
                         cudaFuncAttributeMaxDynamicSharedMemorySize, SMEM_DYN);

    prep_kernel<<<2049, 256>>>(cls, pooled, W, bias, labels, out + 1);   // slot 0
    contrast_kernel<<<NTILES + ZBLK, 256, SMEM_DYN>>>(labels);           // slot 1
    zred_kernel<<<(NLAB * DDIM + 255) / 256, 256>>>();                   // slot 2
    finalize_part<<<2048, 128>>>(labels);                                // slot 3
    finalize_final<<<1, 1024>>>(out);                                    // slot 4
}